// round 6
// baseline (speedup 1.0000x reference)
#include <cuda_runtime.h>

// Fused SegmentationAugmentation, row-hoisted, split-phase, occupancy-6:
//   out[0 .. 2^24)     = trilinear(border) affine sample of input_g   (float)
//   out[2^24 .. 2^25)  = (same sample of label_g) > 0.5               (1.0f/0.0f)
//
// One warp per output (b,d,h) row; lane handles w = lane + 32k, k=0..3.
// T = t @ rot(z) => T[0,2] = T[1,2] = 0, so the x/y pipeline is row-constant
// (warp-uniform fast path; exact generic fallback). Label chain keeps the
// exact reference rounding sequence (__f*_rn, left-assoc); input chain uses
// FMA (tolerance 1e-3, measured 5e-8). k-loop NOT unrolled: trades ILP for
// registers so 6 blocks/SM stay resident.

#define N_VOX (1 << 24)   // 8 * 128^3

__device__ __forceinline__ float unnorm_clamp(float c)
{
    // clip(((c+1)*128 - 1)*0.5, 0, 127) with reference rounding sequence
    return fminf(fmaxf(__fmul_rn(__fsub_rn(__fmul_rn(__fadd_rn(c, 1.0f), 128.0f), 1.0f), 0.5f),
                       0.0f), 127.0f);
}

__global__ __launch_bounds__(256, 6)
void seg_aug_kernel(const float* __restrict__ inp,
                    const float* __restrict__ lab,
                    const float* __restrict__ T,
                    float* __restrict__ out)
{
    const int lane = threadIdx.x & 31;
    const int row  = blockIdx.x * 8 + (threadIdx.x >> 5);  // 131072 rows

    const int h = row & 127;
    const int d = (row >> 7) & 127;
    const int b = row >> 14;

    const float inv128 = 1.0f / 128.0f;
    const float xn = (2.0f * (float)d + 1.0f) * inv128 - 1.0f;
    const float yn = (2.0f * (float)h + 1.0f) * inv128 - 1.0f;
    const float zn0 = (2.0f * (float)lane + 1.0f) * inv128 - 1.0f;

    const float t00 = __ldg(T + 0), t01 = __ldg(T + 1), t02 = __ldg(T + 2),  t03 = __ldg(T + 3);
    const float t10 = __ldg(T + 4), t11 = __ldg(T + 5), t12 = __ldg(T + 6),  t13 = __ldg(T + 7);
    const float t20 = __ldg(T + 8), t21 = __ldg(T + 9), t22 = __ldg(T + 10), t23 = __ldg(T + 11);

    // exact reference prefixes (t0*xn + t1*yn), row-constant
    const float ux = __fadd_rn(__fmul_rn(t00, xn), __fmul_rn(t01, yn));
    const float uy = __fadd_rn(__fmul_rn(t10, xn), __fmul_rn(t11, yn));
    const float uz = __fadd_rn(__fmul_rn(t20, xn), __fmul_rn(t21, yn));

    const int out_base = row << 7;
    const int vol_base = b << 21;

    const bool fastxy = (t02 == 0.0f) && (t12 == 0.0f);   // warp-uniform

    if (fastxy) {
        // hoisted x/y pipeline (bit-exact: adding t02*zn = +/-0 can't change
        // the clamped coordinate)
        const float X = unnorm_clamp(__fadd_rn(ux, t03));
        const float Y = unnorm_clamp(__fadd_rn(uy, t13));
        const float x0f = floorf(X), y0f = floorf(Y);
        const float fx = __fsub_rn(X, x0f);
        const float fy = __fsub_rn(Y, y0f);
        const int x0 = (int)x0f, y0 = (int)y0f;
        const int x1 = min(x0 + 1, 127);
        const int y1 = min(y0 + 1, 127);
        const float wx0 = __fsub_rn(1.0f, fx), wx1 = fx;
        const float wy0 = __fsub_rn(1.0f, fy), wy1 = fy;

        // cached row pointers (one IADD of z per load; no remat)
        const float* pi00 = inp + vol_base + (x0 << 14) + (y0 << 7);
        const float* pi01 = inp + vol_base + (x0 << 14) + (y1 << 7);
        const float* pi10 = inp + vol_base + (x1 << 14) + (y0 << 7);
        const float* pi11 = inp + vol_base + (x1 << 14) + (y1 << 7);
        const float* pl00 = lab + vol_base + (x0 << 14) + (y0 << 7);
        const float* pl01 = lab + vol_base + (x0 << 14) + (y1 << 7);
        const float* pl10 = lab + vol_base + (x1 << 14) + (y0 << 7);
        const float* pl11 = lab + vol_base + (x1 << 14) + (y1 << 7);

        float zn = zn0;
        float* outp = out + out_base + lane;

        #pragma unroll 1
        for (int k = 0; k < 4; k++) {
            const float zs = __fadd_rn(__fadd_rn(uz, __fmul_rn(t22, zn)), t23);
            const float Z = unnorm_clamp(zs);
            const float z0f = floorf(Z);
            const float fz = __fsub_rn(Z, z0f);
            const int z0 = (int)z0f;
            const int z1 = min(z0 + 1, 127);
            const float wz0 = __fsub_rn(1.0f, fz), wz1 = fz;

            // shared exact products (kept live over both phases)
            const float m00 = __fmul_rn(wz0, wy0);
            const float m01 = __fmul_rn(wz0, wy1);
            const float m10 = __fmul_rn(wz1, wy0);
            const float m11 = __fmul_rn(wz1, wy1);

            // ---- phase 1: input volume (FMA allowed, weights JIT) ----
            {
                const float vA = __ldg(pi00 + z0);
                const float vB = __ldg(pi10 + z0);
                const float vC = __ldg(pi01 + z0);
                const float vD = __ldg(pi11 + z0);
                const float vE = __ldg(pi00 + z1);
                const float vF = __ldg(pi10 + z1);
                const float vG = __ldg(pi01 + z1);
                const float vH = __ldg(pi11 + z1);
                float ai = 0.0f;
                ai = fmaf(vA, __fmul_rn(m00, wx0), ai);
                ai = fmaf(vB, __fmul_rn(m00, wx1), ai);
                ai = fmaf(vC, __fmul_rn(m01, wx0), ai);
                ai = fmaf(vD, __fmul_rn(m01, wx1), ai);
                ai = fmaf(vE, __fmul_rn(m10, wx0), ai);
                ai = fmaf(vF, __fmul_rn(m10, wx1), ai);
                ai = fmaf(vG, __fmul_rn(m11, wx0), ai);
                ai = fmaf(vH, __fmul_rn(m11, wx1), ai);
                outp[0] = ai;
            }
            // ---- phase 2: label volume (exact reference sequence) ----
            {
                const float vA = __ldg(pl00 + z0);
                const float vB = __ldg(pl10 + z0);
                const float vC = __ldg(pl01 + z0);
                const float vD = __ldg(pl11 + z0);
                const float vE = __ldg(pl00 + z1);
                const float vF = __ldg(pl10 + z1);
                const float vG = __ldg(pl01 + z1);
                const float vH = __ldg(pl11 + z1);
                float al = 0.0f;
                al = __fadd_rn(al, __fmul_rn(vA, __fmul_rn(m00, wx0)));
                al = __fadd_rn(al, __fmul_rn(vB, __fmul_rn(m00, wx1)));
                al = __fadd_rn(al, __fmul_rn(vC, __fmul_rn(m01, wx0)));
                al = __fadd_rn(al, __fmul_rn(vD, __fmul_rn(m01, wx1)));
                al = __fadd_rn(al, __fmul_rn(vE, __fmul_rn(m10, wx0)));
                al = __fadd_rn(al, __fmul_rn(vF, __fmul_rn(m10, wx1)));
                al = __fadd_rn(al, __fmul_rn(vG, __fmul_rn(m11, wx0)));
                al = __fadd_rn(al, __fmul_rn(vH, __fmul_rn(m11, wx1)));
                outp[N_VOX] = (al > 0.5f) ? 1.0f : 0.0f;
            }

            outp += 32;
            zn += 0.5f;   // exact: multiples of 2^-7, |zn| < 2
        }
    } else {
        // generic exact path (not taken for this transform; kept correct)
        #pragma unroll 1
        for (int k = 0; k < 4; k++) {
            const int w = lane + 32 * k;
            const float zn = (2.0f * (float)w + 1.0f) * inv128 - 1.0f;
            const float xs = __fadd_rn(__fadd_rn(ux, __fmul_rn(t02, zn)), t03);
            const float ys = __fadd_rn(__fadd_rn(uy, __fmul_rn(t12, zn)), t13);
            const float zs = __fadd_rn(__fadd_rn(uz, __fmul_rn(t22, zn)), t23);
            const float X = unnorm_clamp(xs);
            const float Y = unnorm_clamp(ys);
            const float Z = unnorm_clamp(zs);
            const float x0f = floorf(X), y0f = floorf(Y), z0f = floorf(Z);
            const float fx = __fsub_rn(X, x0f);
            const float fy = __fsub_rn(Y, y0f);
            const float fz = __fsub_rn(Z, z0f);
            const int x0 = (int)x0f, y0 = (int)y0f, z0 = (int)z0f;
            const int x1 = min(x0 + 1, 127);
            const int y1 = min(y0 + 1, 127);
            const int z1 = min(z0 + 1, 127);
            const float wx0 = __fsub_rn(1.0f, fx), wx1 = fx;
            const float wy0 = __fsub_rn(1.0f, fy), wy1 = fy;
            const float wz0 = __fsub_rn(1.0f, fz), wz1 = fz;

            const int r00 = vol_base + (x0 << 14) + (y0 << 7);
            const int r01 = vol_base + (x0 << 14) + (y1 << 7);
            const int r10 = vol_base + (x1 << 14) + (y0 << 7);
            const int r11 = vol_base + (x1 << 14) + (y1 << 7);

            const float m00 = __fmul_rn(wz0, wy0);
            const float m01 = __fmul_rn(wz0, wy1);
            const float m10 = __fmul_rn(wz1, wy0);
            const float m11 = __fmul_rn(wz1, wy1);

            float ai = 0.0f;
            ai = __fadd_rn(ai, __fmul_rn(__ldg(inp + r00 + z0), __fmul_rn(m00, wx0)));
            ai = __fadd_rn(ai, __fmul_rn(__ldg(inp + r10 + z0), __fmul_rn(m00, wx1)));
            ai = __fadd_rn(ai, __fmul_rn(__ldg(inp + r01 + z0), __fmul_rn(m01, wx0)));
            ai = __fadd_rn(ai, __fmul_rn(__ldg(inp + r11 + z0), __fmul_rn(m01, wx1)));
            ai = __fadd_rn(ai, __fmul_rn(__ldg(inp + r00 + z1), __fmul_rn(m10, wx0)));
            ai = __fadd_rn(ai, __fmul_rn(__ldg(inp + r10 + z1), __fmul_rn(m10, wx1)));
            ai = __fadd_rn(ai, __fmul_rn(__ldg(inp + r01 + z1), __fmul_rn(m11, wx0)));
            ai = __fadd_rn(ai, __fmul_rn(__ldg(inp + r11 + z1), __fmul_rn(m11, wx1)));
            out[out_base + w] = ai;

            float al = 0.0f;
            al = __fadd_rn(al, __fmul_rn(__ldg(lab + r00 + z0), __fmul_rn(m00, wx0)));
            al = __fadd_rn(al, __fmul_rn(__ldg(lab + r10 + z0), __fmul_rn(m00, wx1)));
            al = __fadd_rn(al, __fmul_rn(__ldg(lab + r01 + z0), __fmul_rn(m01, wx0)));
            al = __fadd_rn(al, __fmul_rn(__ldg(lab + r11 + z0), __fmul_rn(m01, wx1)));
            al = __fadd_rn(al, __fmul_rn(__ldg(lab + r00 + z1), __fmul_rn(m10, wx0)));
            al = __fadd_rn(al, __fmul_rn(__ldg(lab + r10 + z1), __fmul_rn(m10, wx1)));
            al = __fadd_rn(al, __fmul_rn(__ldg(lab + r01 + z1), __fmul_rn(m11, wx0)));
            al = __fadd_rn(al, __fmul_rn(__ldg(lab + r11 + z1), __fmul_rn(m11, wx1)));
            out[out_base + w + N_VOX] = (al > 0.5f) ? 1.0f : 0.0f;
        }
    }
}

extern "C" void kernel_launch(void* const* d_in, const int* in_sizes, int n_in,
                              void* d_out, int out_size)
{
    const float* inp = (const float*)d_in[0];   // input_g  [8,1,128,128,128]
    const float* lab = (const float*)d_in[1];   // label_g  [8,1,128,128,128]
    const float* T   = (const float*)d_in[2];   // transform 4x4 (16 floats)
    float* out = (float*)d_out;

    // 131072 rows, 8 rows (warps) per block
    seg_aug_kernel<<<16384, 256>>>(inp, lab, T, out);
}

// round 7
// speedup vs baseline: 1.8792x; 1.8792x over previous
#include <cuda_runtime.h>

// Fused SegmentationAugmentation, row-hoisted, blended-row (R7):
//   out[0 .. 2^24)     = trilinear(border) affine sample of input_g   (float)
//   out[2^24 .. 2^25)  = (same sample of label_g) > 0.5               (1.0f/0.0f)
//
// One warp per output (b,d,h) row; lane handles w = lane + 32k, k=0..3.
// T = t @ rot(z) => T[0,2] = T[1,2] = 0: x/y pipeline is row-constant.
// INPUT volume: x/y blend factored out per-row into smem (tolerance 1e-3,
//   measured 5e-8 with even stricter math) -> 2 LDS + 2 FMA per voxel.
// LABEL volume: exact reference rounding sequence per voxel (threshold at
//   0.5 requires bit-exactness): 8 gathers + left-assoc no-FMA chain.

#define N_VOX (1 << 24)   // 8 * 128^3

__device__ __forceinline__ float unnorm_clamp(float c)
{
    // clip(((c+1)*128 - 1)*0.5, 0, 127) with reference rounding sequence
    return fminf(fmaxf(__fmul_rn(__fsub_rn(__fmul_rn(__fadd_rn(c, 1.0f), 128.0f), 1.0f), 0.5f),
                       0.0f), 127.0f);
}

__global__ __launch_bounds__(256, 5)
void seg_aug_kernel(const float* __restrict__ inp,
                    const float* __restrict__ lab,
                    const float* __restrict__ T,
                    float* __restrict__ out)
{
    __shared__ float s_brow[8][128];   // blended input row per warp (4KB)

    const int lane = threadIdx.x & 31;
    const int wid  = threadIdx.x >> 5;
    const int row  = blockIdx.x * 8 + wid;  // 131072 rows

    const int h = row & 127;
    const int d = (row >> 7) & 127;
    const int b = row >> 14;

    const float inv128 = 1.0f / 128.0f;
    const float xn = (2.0f * (float)d + 1.0f) * inv128 - 1.0f;
    const float yn = (2.0f * (float)h + 1.0f) * inv128 - 1.0f;
    const float zn0 = (2.0f * (float)lane + 1.0f) * inv128 - 1.0f;

    const float t00 = __ldg(T + 0), t01 = __ldg(T + 1), t02 = __ldg(T + 2),  t03 = __ldg(T + 3);
    const float t10 = __ldg(T + 4), t11 = __ldg(T + 5), t12 = __ldg(T + 6),  t13 = __ldg(T + 7);
    const float t20 = __ldg(T + 8), t21 = __ldg(T + 9), t22 = __ldg(T + 10), t23 = __ldg(T + 11);

    // exact reference prefixes (t0*xn + t1*yn), row-constant
    const float ux = __fadd_rn(__fmul_rn(t00, xn), __fmul_rn(t01, yn));
    const float uy = __fadd_rn(__fmul_rn(t10, xn), __fmul_rn(t11, yn));
    const float uz = __fadd_rn(__fmul_rn(t20, xn), __fmul_rn(t21, yn));

    const int out_base = row << 7;
    const int vol_base = b << 21;

    const bool fastxy = (t02 == 0.0f) && (t12 == 0.0f);   // warp-uniform

    if (fastxy) {
        // hoisted x/y pipeline (bit-exact: adding t02*zn = +/-0 can't change
        // the clamped coordinate)
        const float X = unnorm_clamp(__fadd_rn(ux, t03));
        const float Y = unnorm_clamp(__fadd_rn(uy, t13));
        const float x0f = floorf(X), y0f = floorf(Y);
        const float fx = __fsub_rn(X, x0f);
        const float fy = __fsub_rn(Y, y0f);
        const int x0 = (int)x0f, y0 = (int)y0f;
        const int x1 = min(x0 + 1, 127);
        const int y1 = min(y0 + 1, 127);
        const float wx0 = __fsub_rn(1.0f, fx), wx1 = fx;
        const float wy0 = __fsub_rn(1.0f, fy), wy1 = fy;

        // ---- stage blended input row into smem (free rounding) ----
        {
            const float4* q00 = (const float4*)(inp + vol_base + (x0 << 14) + (y0 << 7));
            const float4* q10 = (const float4*)(inp + vol_base + (x1 << 14) + (y0 << 7));
            const float4* q01 = (const float4*)(inp + vol_base + (x0 << 14) + (y1 << 7));
            const float4* q11 = (const float4*)(inp + vol_base + (x1 << 14) + (y1 << 7));
            const float wxy00 = wx0 * wy0;
            const float wxy10 = wx1 * wy0;
            const float wxy01 = wx0 * wy1;
            const float wxy11 = wx1 * wy1;
            const float4 a = __ldg(q00 + lane);
            const float4 c = __ldg(q10 + lane);
            const float4 e = __ldg(q01 + lane);
            const float4 g = __ldg(q11 + lane);
            float4 bl;
            bl.x = fmaf(a.x, wxy00, fmaf(c.x, wxy10, fmaf(e.x, wxy01, g.x * wxy11)));
            bl.y = fmaf(a.y, wxy00, fmaf(c.y, wxy10, fmaf(e.y, wxy01, g.y * wxy11)));
            bl.z = fmaf(a.z, wxy00, fmaf(c.z, wxy10, fmaf(e.z, wxy01, g.z * wxy11)));
            bl.w = fmaf(a.w, wxy00, fmaf(c.w, wxy10, fmaf(e.w, wxy01, g.w * wxy11)));
            ((float4*)s_brow[wid])[lane] = bl;
        }
        __syncwarp();
        const float* brow = s_brow[wid];

        // label row pointers (exact path still gathers)
        const float* pl00 = lab + vol_base + (x0 << 14) + (y0 << 7);
        const float* pl01 = lab + vol_base + (x0 << 14) + (y1 << 7);
        const float* pl10 = lab + vol_base + (x1 << 14) + (y0 << 7);
        const float* pl11 = lab + vol_base + (x1 << 14) + (y1 << 7);

        #pragma unroll
        for (int k = 0; k < 4; k++) {
            const float zn = zn0 + 0.5f * (float)k;   // exact (multiples of 2^-7)
            const float zs = __fadd_rn(__fadd_rn(uz, __fmul_rn(t22, zn)), t23);
            const float Z = unnorm_clamp(zs);
            const float z0f = floorf(Z);
            const float fz = __fsub_rn(Z, z0f);
            const int z0 = (int)z0f;
            const int z1 = min(z0 + 1, 127);
            const float wz0 = __fsub_rn(1.0f, fz), wz1 = fz;

            const int idx = out_base + lane + 32 * k;

            // ---- input: 2 LDS + 2 FMA ----
            out[idx] = fmaf(brow[z0], wz0, brow[z1] * wz1);

            // ---- label: exact reference sequence ----
            {
                const float m00 = __fmul_rn(wz0, wy0);
                const float m01 = __fmul_rn(wz0, wy1);
                const float m10 = __fmul_rn(wz1, wy0);
                const float m11 = __fmul_rn(wz1, wy1);
                const float vA = __ldg(pl00 + z0);
                const float vB = __ldg(pl10 + z0);
                const float vC = __ldg(pl01 + z0);
                const float vD = __ldg(pl11 + z0);
                const float vE = __ldg(pl00 + z1);
                const float vF = __ldg(pl10 + z1);
                const float vG = __ldg(pl01 + z1);
                const float vH = __ldg(pl11 + z1);
                float al = 0.0f;
                al = __fadd_rn(al, __fmul_rn(vA, __fmul_rn(m00, wx0)));
                al = __fadd_rn(al, __fmul_rn(vB, __fmul_rn(m00, wx1)));
                al = __fadd_rn(al, __fmul_rn(vC, __fmul_rn(m01, wx0)));
                al = __fadd_rn(al, __fmul_rn(vD, __fmul_rn(m01, wx1)));
                al = __fadd_rn(al, __fmul_rn(vE, __fmul_rn(m10, wx0)));
                al = __fadd_rn(al, __fmul_rn(vF, __fmul_rn(m10, wx1)));
                al = __fadd_rn(al, __fmul_rn(vG, __fmul_rn(m11, wx0)));
                al = __fadd_rn(al, __fmul_rn(vH, __fmul_rn(m11, wx1)));
                out[idx + N_VOX] = (al > 0.5f) ? 1.0f : 0.0f;
            }
        }
    } else {
        // generic exact path (not taken for this transform; kept correct)
        #pragma unroll 1
        for (int k = 0; k < 4; k++) {
            const int w = lane + 32 * k;
            const float zn = (2.0f * (float)w + 1.0f) * inv128 - 1.0f;
            const float xs = __fadd_rn(__fadd_rn(ux, __fmul_rn(t02, zn)), t03);
            const float ys = __fadd_rn(__fadd_rn(uy, __fmul_rn(t12, zn)), t13);
            const float zs = __fadd_rn(__fadd_rn(uz, __fmul_rn(t22, zn)), t23);
            const float X = unnorm_clamp(xs);
            const float Y = unnorm_clamp(ys);
            const float Z = unnorm_clamp(zs);
            const float x0f = floorf(X), y0f = floorf(Y), z0f = floorf(Z);
            const float fx = __fsub_rn(X, x0f);
            const float fy = __fsub_rn(Y, y0f);
            const float fz = __fsub_rn(Z, z0f);
            const int x0 = (int)x0f, y0 = (int)y0f, z0 = (int)z0f;
            const int x1 = min(x0 + 1, 127);
            const int y1 = min(y0 + 1, 127);
            const int z1 = min(z0 + 1, 127);
            const float wx0 = __fsub_rn(1.0f, fx), wx1 = fx;
            const float wy0 = __fsub_rn(1.0f, fy), wy1 = fy;
            const float wz0 = __fsub_rn(1.0f, fz), wz1 = fz;

            const int r00 = vol_base + (x0 << 14) + (y0 << 7);
            const int r01 = vol_base + (x0 << 14) + (y1 << 7);
            const int r10 = vol_base + (x1 << 14) + (y0 << 7);
            const int r11 = vol_base + (x1 << 14) + (y1 << 7);

            const float m00 = __fmul_rn(wz0, wy0);
            const float m01 = __fmul_rn(wz0, wy1);
            const float m10 = __fmul_rn(wz1, wy0);
            const float m11 = __fmul_rn(wz1, wy1);

            float ai = 0.0f;
            ai = __fadd_rn(ai, __fmul_rn(__ldg(inp + r00 + z0), __fmul_rn(m00, wx0)));
            ai = __fadd_rn(ai, __fmul_rn(__ldg(inp + r10 + z0), __fmul_rn(m00, wx1)));
            ai = __fadd_rn(ai, __fmul_rn(__ldg(inp + r01 + z0), __fmul_rn(m01, wx0)));
            ai = __fadd_rn(ai, __fmul_rn(__ldg(inp + r11 + z0), __fmul_rn(m01, wx1)));
            ai = __fadd_rn(ai, __fmul_rn(__ldg(inp + r00 + z1), __fmul_rn(m10, wx0)));
            ai = __fadd_rn(ai, __fmul_rn(__ldg(inp + r10 + z1), __fmul_rn(m10, wx1)));
            ai = __fadd_rn(ai, __fmul_rn(__ldg(inp + r01 + z1), __fmul_rn(m11, wx0)));
            ai = __fadd_rn(ai, __fmul_rn(__ldg(inp + r11 + z1), __fmul_rn(m11, wx1)));
            out[out_base + w] = ai;

            float al = 0.0f;
            al = __fadd_rn(al, __fmul_rn(__ldg(lab + r00 + z0), __fmul_rn(m00, wx0)));
            al = __fadd_rn(al, __fmul_rn(__ldg(lab + r10 + z0), __fmul_rn(m00, wx1)));
            al = __fadd_rn(al, __fmul_rn(__ldg(lab + r01 + z0), __fmul_rn(m01, wx0)));
            al = __fadd_rn(al, __fmul_rn(__ldg(lab + r11 + z0), __fmul_rn(m01, wx1)));
            al = __fadd_rn(al, __fmul_rn(__ldg(lab + r00 + z1), __fmul_rn(m10, wx0)));
            al = __fadd_rn(al, __fmul_rn(__ldg(lab + r10 + z1), __fmul_rn(m10, wx1)));
            al = __fadd_rn(al, __fmul_rn(__ldg(lab + r01 + z1), __fmul_rn(m11, wx0)));
            al = __fadd_rn(al, __fmul_rn(__ldg(lab + r11 + z1), __fmul_rn(m11, wx1)));
            out[out_base + w + N_VOX] = (al > 0.5f) ? 1.0f : 0.0f;
        }
    }
}

extern "C" void kernel_launch(void* const* d_in, const int* in_sizes, int n_in,
                              void* d_out, int out_size)
{
    const float* inp = (const float*)d_in[0];   // input_g  [8,1,128,128,128]
    const float* lab = (const float*)d_in[1];   // label_g  [8,1,128,128,128]
    const float* T   = (const float*)d_in[2];   // transform 4x4 (16 floats)
    float* out = (float*)d_out;

    // 131072 rows, 8 rows (warps) per block
    seg_aug_kernel<<<16384, 256>>>(inp, lab, T, out);
}

// round 8
// speedup vs baseline: 1.9514x; 1.0384x over previous
#include <cuda_runtime.h>

// Fused SegmentationAugmentation, row-hoisted, smem-staged (R8):
//   out[0 .. 2^24)     = trilinear(border) affine sample of input_g   (float)
//   out[2^24 .. 2^25)  = (same sample of label_g) > 0.5               (1.0f/0.0f)
//
// One warp per output (b,d,h) row; lane handles w = lane + 32k, k=0..3.
// T = t @ rot(z) => T[0,2] = T[1,2] = 0: x/y pipeline is row-constant.
// INPUT:  x/y blend factored per-row into smem -> 2 LDS + 2 FMA per voxel.
// LABEL:  4 source rows staged into smem via float4 loads; per-voxel exact
//         reference rounding chain reads LDS copies (bit-identical values).

#define N_VOX (1 << 24)   // 8 * 128^3

__device__ __forceinline__ float unnorm_clamp(float c)
{
    // clip(((c+1)*128 - 1)*0.5, 0, 127) with reference rounding sequence
    return fminf(fmaxf(__fmul_rn(__fsub_rn(__fmul_rn(__fadd_rn(c, 1.0f), 128.0f), 1.0f), 0.5f),
                       0.0f), 127.0f);
}

__global__ __launch_bounds__(256, 5)
void seg_aug_kernel(const float* __restrict__ inp,
                    const float* __restrict__ lab,
                    const float* __restrict__ T,
                    float* __restrict__ out)
{
    __shared__ float s_brow[8][128];      // blended input row per warp (4KB)
    __shared__ float s_lab[8][4][128];    // 4 raw label rows per warp (16KB)

    const int lane = threadIdx.x & 31;
    const int wid  = threadIdx.x >> 5;
    const int row  = blockIdx.x * 8 + wid;  // 131072 rows

    const int h = row & 127;
    const int d = (row >> 7) & 127;
    const int b = row >> 14;

    const float inv128 = 1.0f / 128.0f;
    const float xn = (2.0f * (float)d + 1.0f) * inv128 - 1.0f;
    const float yn = (2.0f * (float)h + 1.0f) * inv128 - 1.0f;
    const float zn0 = (2.0f * (float)lane + 1.0f) * inv128 - 1.0f;

    const float t00 = __ldg(T + 0), t01 = __ldg(T + 1), t02 = __ldg(T + 2),  t03 = __ldg(T + 3);
    const float t10 = __ldg(T + 4), t11 = __ldg(T + 5), t12 = __ldg(T + 6),  t13 = __ldg(T + 7);
    const float t20 = __ldg(T + 8), t21 = __ldg(T + 9), t22 = __ldg(T + 10), t23 = __ldg(T + 11);

    // exact reference prefixes (t0*xn + t1*yn), row-constant
    const float ux = __fadd_rn(__fmul_rn(t00, xn), __fmul_rn(t01, yn));
    const float uy = __fadd_rn(__fmul_rn(t10, xn), __fmul_rn(t11, yn));
    const float uz = __fadd_rn(__fmul_rn(t20, xn), __fmul_rn(t21, yn));

    const int out_base = row << 7;
    const int vol_base = b << 21;

    const bool fastxy = (t02 == 0.0f) && (t12 == 0.0f);   // warp-uniform

    if (fastxy) {
        // hoisted x/y pipeline (bit-exact: adding t02*zn = +/-0 can't change
        // the clamped coordinate)
        const float X = unnorm_clamp(__fadd_rn(ux, t03));
        const float Y = unnorm_clamp(__fadd_rn(uy, t13));
        const float x0f = floorf(X), y0f = floorf(Y);
        const float fx = __fsub_rn(X, x0f);
        const float fy = __fsub_rn(Y, y0f);
        const int x0 = (int)x0f, y0 = (int)y0f;
        const int x1 = min(x0 + 1, 127);
        const int y1 = min(y0 + 1, 127);
        const float wx0 = __fsub_rn(1.0f, fx), wx1 = fx;
        const float wy0 = __fsub_rn(1.0f, fy), wy1 = fy;

        const int r00 = vol_base + (x0 << 14) + (y0 << 7);  // A: (x0,y0)
        const int r10 = vol_base + (x1 << 14) + (y0 << 7);  // B: (x1,y0)
        const int r01 = vol_base + (x0 << 14) + (y1 << 7);  // C: (x0,y1)
        const int r11 = vol_base + (x1 << 14) + (y1 << 7);  // D: (x1,y1)

        // ---- stage blended input row (free rounding) ----
        {
            const float wxy00 = wx0 * wy0;
            const float wxy10 = wx1 * wy0;
            const float wxy01 = wx0 * wy1;
            const float wxy11 = wx1 * wy1;
            const float4 a = __ldg((const float4*)(inp + r00) + lane);
            const float4 c = __ldg((const float4*)(inp + r10) + lane);
            const float4 e = __ldg((const float4*)(inp + r01) + lane);
            const float4 g = __ldg((const float4*)(inp + r11) + lane);
            float4 bl;
            bl.x = fmaf(a.x, wxy00, fmaf(c.x, wxy10, fmaf(e.x, wxy01, g.x * wxy11)));
            bl.y = fmaf(a.y, wxy00, fmaf(c.y, wxy10, fmaf(e.y, wxy01, g.y * wxy11)));
            bl.z = fmaf(a.z, wxy00, fmaf(c.z, wxy10, fmaf(e.z, wxy01, g.z * wxy11)));
            bl.w = fmaf(a.w, wxy00, fmaf(c.w, wxy10, fmaf(e.w, wxy01, g.w * wxy11)));
            ((float4*)s_brow[wid])[lane] = bl;
        }
        // ---- stage 4 raw label rows (bit-identical copies) ----
        {
            ((float4*)s_lab[wid][0])[lane] = __ldg((const float4*)(lab + r00) + lane);
            ((float4*)s_lab[wid][1])[lane] = __ldg((const float4*)(lab + r10) + lane);
            ((float4*)s_lab[wid][2])[lane] = __ldg((const float4*)(lab + r01) + lane);
            ((float4*)s_lab[wid][3])[lane] = __ldg((const float4*)(lab + r11) + lane);
        }
        __syncwarp();

        const float* brow = s_brow[wid];
        const float* lA = s_lab[wid][0];   // (x0,y0)
        const float* lB = s_lab[wid][1];   // (x1,y0)
        const float* lC = s_lab[wid][2];   // (x0,y1)
        const float* lD = s_lab[wid][3];   // (x1,y1)

        #pragma unroll
        for (int k = 0; k < 4; k++) {
            const float zn = zn0 + 0.5f * (float)k;   // exact (multiples of 2^-7)
            const float zs = __fadd_rn(__fadd_rn(uz, __fmul_rn(t22, zn)), t23);
            const float Z = unnorm_clamp(zs);
            const float z0f = floorf(Z);
            const float fz = __fsub_rn(Z, z0f);
            const int z0 = (int)z0f;
            const int z1 = min(z0 + 1, 127);
            const float wz0 = __fsub_rn(1.0f, fz), wz1 = fz;

            const int idx = out_base + lane + 32 * k;

            // ---- input: 2 LDS + 2 FMA ----
            out[idx] = fmaf(brow[z0], wz0, brow[z1] * wz1);

            // ---- label: exact reference sequence (LDS sources) ----
            {
                const float m00 = __fmul_rn(wz0, wy0);
                const float m01 = __fmul_rn(wz0, wy1);
                const float m10 = __fmul_rn(wz1, wy0);
                const float m11 = __fmul_rn(wz1, wy1);
                float al = 0.0f;
                al = __fadd_rn(al, __fmul_rn(lA[z0], __fmul_rn(m00, wx0)));
                al = __fadd_rn(al, __fmul_rn(lB[z0], __fmul_rn(m00, wx1)));
                al = __fadd_rn(al, __fmul_rn(lC[z0], __fmul_rn(m01, wx0)));
                al = __fadd_rn(al, __fmul_rn(lD[z0], __fmul_rn(m01, wx1)));
                al = __fadd_rn(al, __fmul_rn(lA[z1], __fmul_rn(m10, wx0)));
                al = __fadd_rn(al, __fmul_rn(lB[z1], __fmul_rn(m10, wx1)));
                al = __fadd_rn(al, __fmul_rn(lC[z1], __fmul_rn(m11, wx0)));
                al = __fadd_rn(al, __fmul_rn(lD[z1], __fmul_rn(m11, wx1)));
                out[idx + N_VOX] = (al > 0.5f) ? 1.0f : 0.0f;
            }
        }
    } else {
        // generic exact path (not taken for this transform; kept correct)
        #pragma unroll 1
        for (int k = 0; k < 4; k++) {
            const int w = lane + 32 * k;
            const float zn = (2.0f * (float)w + 1.0f) * inv128 - 1.0f;
            const float xs = __fadd_rn(__fadd_rn(ux, __fmul_rn(t02, zn)), t03);
            const float ys = __fadd_rn(__fadd_rn(uy, __fmul_rn(t12, zn)), t13);
            const float zs = __fadd_rn(__fadd_rn(uz, __fmul_rn(t22, zn)), t23);
            const float X = unnorm_clamp(xs);
            const float Y = unnorm_clamp(ys);
            const float Z = unnorm_clamp(zs);
            const float x0f = floorf(X), y0f = floorf(Y), z0f = floorf(Z);
            const float fx = __fsub_rn(X, x0f);
            const float fy = __fsub_rn(Y, y0f);
            const float fz = __fsub_rn(Z, z0f);
            const int x0 = (int)x0f, y0 = (int)y0f, z0 = (int)z0f;
            const int x1 = min(x0 + 1, 127);
            const int y1 = min(y0 + 1, 127);
            const int z1 = min(z0 + 1, 127);
            const float wx0 = __fsub_rn(1.0f, fx), wx1 = fx;
            const float wy0 = __fsub_rn(1.0f, fy), wy1 = fy;
            const float wz0 = __fsub_rn(1.0f, fz), wz1 = fz;

            const int r00 = vol_base + (x0 << 14) + (y0 << 7);
            const int r01 = vol_base + (x0 << 14) + (y1 << 7);
            const int r10 = vol_base + (x1 << 14) + (y0 << 7);
            const int r11 = vol_base + (x1 << 14) + (y1 << 7);

            const float m00 = __fmul_rn(wz0, wy0);
            const float m01 = __fmul_rn(wz0, wy1);
            const float m10 = __fmul_rn(wz1, wy0);
            const float m11 = __fmul_rn(wz1, wy1);

            float ai = 0.0f;
            ai = __fadd_rn(ai, __fmul_rn(__ldg(inp + r00 + z0), __fmul_rn(m00, wx0)));
            ai = __fadd_rn(ai, __fmul_rn(__ldg(inp + r10 + z0), __fmul_rn(m00, wx1)));
            ai = __fadd_rn(ai, __fmul_rn(__ldg(inp + r01 + z0), __fmul_rn(m01, wx0)));
            ai = __fadd_rn(ai, __fmul_rn(__ldg(inp + r11 + z0), __fmul_rn(m01, wx1)));
            ai = __fadd_rn(ai, __fmul_rn(__ldg(inp + r00 + z1), __fmul_rn(m10, wx0)));
            ai = __fadd_rn(ai, __fmul_rn(__ldg(inp + r10 + z1), __fmul_rn(m10, wx1)));
            ai = __fadd_rn(ai, __fmul_rn(__ldg(inp + r01 + z1), __fmul_rn(m11, wx0)));
            ai = __fadd_rn(ai, __fmul_rn(__ldg(inp + r11 + z1), __fmul_rn(m11, wx1)));
            out[out_base + w] = ai;

            float al = 0.0f;
            al = __fadd_rn(al, __fmul_rn(__ldg(lab + r00 + z0), __fmul_rn(m00, wx0)));
            al = __fadd_rn(al, __fmul_rn(__ldg(lab + r10 + z0), __fmul_rn(m00, wx1)));
            al = __fadd_rn(al, __fmul_rn(__ldg(lab + r01 + z0), __fmul_rn(m01, wx0)));
            al = __fadd_rn(al, __fmul_rn(__ldg(lab + r11 + z0), __fmul_rn(m01, wx1)));
            al = __fadd_rn(al, __fmul_rn(__ldg(lab + r00 + z1), __fmul_rn(m10, wx0)));
            al = __fadd_rn(al, __fmul_rn(__ldg(lab + r10 + z1), __fmul_rn(m10, wx1)));
            al = __fadd_rn(al, __fmul_rn(__ldg(lab + r01 + z1), __fmul_rn(m11, wx0)));
            al = __fadd_rn(al, __fmul_rn(__ldg(lab + r11 + z1), __fmul_rn(m11, wx1)));
            out[out_base + w + N_VOX] = (al > 0.5f) ? 1.0f : 0.0f;
        }
    }
}

extern "C" void kernel_launch(void* const* d_in, const int* in_sizes, int n_in,
                              void* d_out, int out_size)
{
    const float* inp = (const float*)d_in[0];   // input_g  [8,1,128,128,128]
    const float* lab = (const float*)d_in[1];   // label_g  [8,1,128,128,128]
    const float* T   = (const float*)d_in[2];   // transform 4x4 (16 floats)
    float* out = (float*)d_out;

    // 131072 rows, 8 rows (warps) per block
    seg_aug_kernel<<<16384, 256>>>(inp, lab, T, out);
}

// round 10
// speedup vs baseline: 2.2588x; 1.1575x over previous
#include <cuda_runtime.h>
#include <cstdint>

// Fused SegmentationAugmentation, row-hoisted, cp.async-staged (R10):
//   out[0 .. 2^24)     = trilinear(border) affine sample of input_g   (float)
//   out[2^24 .. 2^25)  = (same sample of label_g) > 0.5               (1.0f/0.0f)
//
// One warp per output (b,d,h) row; lane handles w = lane + 32k, k=0..3.
// T = t @ rot(z) => T[0,2] = T[1,2] = 0: x/y pipeline is row-constant.
// INPUT:  x/y blend factored per-row into smem -> 2 LDS + 2 FMA per voxel.
// LABEL:  4 raw rows copied gmem->smem via cp.async (no STS/register leg);
//         per-voxel exact reference rounding chain reads bit-identical
//         LDS copies.

#define N_VOX (1 << 24)   // 8 * 128^3

__device__ __forceinline__ float unnorm_clamp(float c)
{
    // clip(((c+1)*128 - 1)*0.5, 0, 127) with reference rounding sequence
    return fminf(fmaxf(__fmul_rn(__fsub_rn(__fmul_rn(__fadd_rn(c, 1.0f), 128.0f), 1.0f), 0.5f),
                       0.0f), 127.0f);
}

__device__ __forceinline__ void cp_async16(uint32_t smem_addr, const void* gmem)
{
    asm volatile("cp.async.cg.shared.global [%0], [%1], 16;\n"
                 :: "r"(smem_addr), "l"(gmem));
}

__global__ __launch_bounds__(256, 5)
void seg_aug_kernel(const float* __restrict__ inp,
                    const float* __restrict__ lab,
                    const float* __restrict__ T,
                    float* __restrict__ out)
{
    __shared__ float s_brow[8][128];      // blended input row per warp (4KB)
    __shared__ float s_lab[8][4][128];    // 4 raw label rows per warp (16KB)

    const int lane = threadIdx.x & 31;
    const int wid  = threadIdx.x >> 5;
    const int row  = blockIdx.x * 8 + wid;  // 131072 rows

    const int h = row & 127;
    const int d = (row >> 7) & 127;
    const int b = row >> 14;

    const float inv128 = 1.0f / 128.0f;
    const float xn = (2.0f * (float)d + 1.0f) * inv128 - 1.0f;
    const float yn = (2.0f * (float)h + 1.0f) * inv128 - 1.0f;
    const float zn0 = (2.0f * (float)lane + 1.0f) * inv128 - 1.0f;

    const float t00 = __ldg(T + 0), t01 = __ldg(T + 1), t02 = __ldg(T + 2),  t03 = __ldg(T + 3);
    const float t10 = __ldg(T + 4), t11 = __ldg(T + 5), t12 = __ldg(T + 6),  t13 = __ldg(T + 7);
    const float t20 = __ldg(T + 8), t21 = __ldg(T + 9), t22 = __ldg(T + 10), t23 = __ldg(T + 11);

    // exact reference prefixes (t0*xn + t1*yn), row-constant
    const float ux = __fadd_rn(__fmul_rn(t00, xn), __fmul_rn(t01, yn));
    const float uy = __fadd_rn(__fmul_rn(t10, xn), __fmul_rn(t11, yn));
    const float uz = __fadd_rn(__fmul_rn(t20, xn), __fmul_rn(t21, yn));

    const int out_base = row << 7;
    const int vol_base = b << 21;

    const bool fastxy = (t02 == 0.0f) && (t12 == 0.0f);   // warp-uniform

    if (fastxy) {
        // hoisted x/y pipeline (bit-exact: adding t02*zn = +/-0 can't change
        // the clamped coordinate)
        const float X = unnorm_clamp(__fadd_rn(ux, t03));
        const float Y = unnorm_clamp(__fadd_rn(uy, t13));
        const float x0f = floorf(X), y0f = floorf(Y);
        const float fx = __fsub_rn(X, x0f);
        const float fy = __fsub_rn(Y, y0f);
        const int x0 = (int)x0f, y0 = (int)y0f;
        const int x1 = min(x0 + 1, 127);
        const int y1 = min(y0 + 1, 127);
        const float wx0 = __fsub_rn(1.0f, fx), wx1 = fx;
        const float wy0 = __fsub_rn(1.0f, fy), wy1 = fy;

        const int r00 = vol_base + (x0 << 14) + (y0 << 7);  // A: (x0,y0)
        const int r10 = vol_base + (x1 << 14) + (y0 << 7);  // B: (x1,y0)
        const int r01 = vol_base + (x0 << 14) + (y1 << 7);  // C: (x0,y1)
        const int r11 = vol_base + (x1 << 14) + (y1 << 7);  // D: (x1,y1)

        // ---- stage 4 raw label rows via cp.async (no register leg) ----
        {
            const uint32_t sbase = (uint32_t)__cvta_generic_to_shared(&s_lab[wid][0][0])
                                 + (uint32_t)(lane * 16);
            cp_async16(sbase,            lab + r00 + lane * 4);
            cp_async16(sbase + 512,      lab + r10 + lane * 4);
            cp_async16(sbase + 1024,     lab + r01 + lane * 4);
            cp_async16(sbase + 1536,     lab + r11 + lane * 4);
            asm volatile("cp.async.commit_group;\n" ::: "memory");
        }

        // ---- stage blended input row (overlaps the cp.asyncs) ----
        {
            const float wxy00 = wx0 * wy0;
            const float wxy10 = wx1 * wy0;
            const float wxy01 = wx0 * wy1;
            const float wxy11 = wx1 * wy1;
            const float4 a = __ldg((const float4*)(inp + r00) + lane);
            const float4 c = __ldg((const float4*)(inp + r10) + lane);
            const float4 e = __ldg((const float4*)(inp + r01) + lane);
            const float4 g = __ldg((const float4*)(inp + r11) + lane);
            float4 bl;
            bl.x = fmaf(a.x, wxy00, fmaf(c.x, wxy10, fmaf(e.x, wxy01, g.x * wxy11)));
            bl.y = fmaf(a.y, wxy00, fmaf(c.y, wxy10, fmaf(e.y, wxy01, g.y * wxy11)));
            bl.z = fmaf(a.z, wxy00, fmaf(c.z, wxy10, fmaf(e.z, wxy01, g.z * wxy11)));
            bl.w = fmaf(a.w, wxy00, fmaf(c.w, wxy10, fmaf(e.w, wxy01, g.w * wxy11)));
            ((float4*)s_brow[wid])[lane] = bl;
        }

        asm volatile("cp.async.wait_group 0;\n" ::: "memory");
        __syncwarp();

        const float* brow = s_brow[wid];
        const float* lA = s_lab[wid][0];   // (x0,y0)
        const float* lB = s_lab[wid][1];   // (x1,y0)
        const float* lC = s_lab[wid][2];   // (x0,y1)
        const float* lD = s_lab[wid][3];   // (x1,y1)

        #pragma unroll
        for (int k = 0; k < 4; k++) {
            const float zn = zn0 + 0.5f * (float)k;   // exact (multiples of 2^-7)
            const float zs = __fadd_rn(__fadd_rn(uz, __fmul_rn(t22, zn)), t23);
            const float Z = unnorm_clamp(zs);
            const float z0f = floorf(Z);
            const float fz = __fsub_rn(Z, z0f);
            const int z0 = (int)z0f;
            const int z1 = min(z0 + 1, 127);
            const float wz0 = __fsub_rn(1.0f, fz), wz1 = fz;

            const int idx = out_base + lane + 32 * k;

            // ---- input: 2 LDS + 2 FMA ----
            out[idx] = fmaf(brow[z0], wz0, brow[z1] * wz1);

            // ---- label: exact reference sequence (LDS sources) ----
            {
                const float m00 = __fmul_rn(wz0, wy0);
                const float m01 = __fmul_rn(wz0, wy1);
                const float m10 = __fmul_rn(wz1, wy0);
                const float m11 = __fmul_rn(wz1, wy1);
                const float wA = __fmul_rn(m00, wx0), wB = __fmul_rn(m00, wx1);
                const float wC = __fmul_rn(m01, wx0), wD = __fmul_rn(m01, wx1);
                const float wE = __fmul_rn(m10, wx0), wF = __fmul_rn(m10, wx1);
                const float wG = __fmul_rn(m11, wx0), wH = __fmul_rn(m11, wx1);
                float al = 0.0f;
                al = __fadd_rn(al, __fmul_rn(lA[z0], wA));
                al = __fadd_rn(al, __fmul_rn(lB[z0], wB));
                al = __fadd_rn(al, __fmul_rn(lC[z0], wC));
                al = __fadd_rn(al, __fmul_rn(lD[z0], wD));
                al = __fadd_rn(al, __fmul_rn(lA[z1], wE));
                al = __fadd_rn(al, __fmul_rn(lB[z1], wF));
                al = __fadd_rn(al, __fmul_rn(lC[z1], wG));
                al = __fadd_rn(al, __fmul_rn(lD[z1], wH));
                out[idx + N_VOX] = (al > 0.5f) ? 1.0f : 0.0f;
            }
        }
    } else {
        // generic exact path (not taken for this transform; kept correct)
        #pragma unroll 1
        for (int k = 0; k < 4; k++) {
            const int w = lane + 32 * k;
            const float zn = (2.0f * (float)w + 1.0f) * inv128 - 1.0f;
            const float xs = __fadd_rn(__fadd_rn(ux, __fmul_rn(t02, zn)), t03);
            const float ys = __fadd_rn(__fadd_rn(uy, __fmul_rn(t12, zn)), t13);
            const float zs = __fadd_rn(__fadd_rn(uz, __fmul_rn(t22, zn)), t23);
            const float X = unnorm_clamp(xs);
            const float Y = unnorm_clamp(ys);
            const float Z = unnorm_clamp(zs);
            const float x0f = floorf(X), y0f = floorf(Y), z0f = floorf(Z);
            const float fx = __fsub_rn(X, x0f);
            const float fy = __fsub_rn(Y, y0f);
            const float fz = __fsub_rn(Z, z0f);
            const int x0 = (int)x0f, y0 = (int)y0f, z0 = (int)z0f;
            const int x1 = min(x0 + 1, 127);
            const int y1 = min(y0 + 1, 127);
            const int z1 = min(z0 + 1, 127);
            const float wx0 = __fsub_rn(1.0f, fx), wx1 = fx;
            const float wy0 = __fsub_rn(1.0f, fy), wy1 = fy;
            const float wz0 = __fsub_rn(1.0f, fz), wz1 = fz;

            const int r00 = vol_base + (x0 << 14) + (y0 << 7);
            const int r01 = vol_base + (x0 << 14) + (y1 << 7);
            const int r10 = vol_base + (x1 << 14) + (y0 << 7);
            const int r11 = vol_base + (x1 << 14) + (y1 << 7);

            const float m00 = __fmul_rn(wz0, wy0);
            const float m01 = __fmul_rn(wz0, wy1);
            const float m10 = __fmul_rn(wz1, wy0);
            const float m11 = __fmul_rn(wz1, wy1);

            float ai = 0.0f;
            ai = __fadd_rn(ai, __fmul_rn(__ldg(inp + r00 + z0), __fmul_rn(m00, wx0)));
            ai = __fadd_rn(ai, __fmul_rn(__ldg(inp + r10 + z0), __fmul_rn(m00, wx1)));
            ai = __fadd_rn(ai, __fmul_rn(__ldg(inp + r01 + z0), __fmul_rn(m01, wx0)));
            ai = __fadd_rn(ai, __fmul_rn(__ldg(inp + r11 + z0), __fmul_rn(m01, wx1)));
            ai = __fadd_rn(ai, __fmul_rn(__ldg(inp + r00 + z1), __fmul_rn(m10, wx0)));
            ai = __fadd_rn(ai, __fmul_rn(__ldg(inp + r10 + z1), __fmul_rn(m10, wx1)));
            ai = __fadd_rn(ai, __fmul_rn(__ldg(inp + r01 + z1), __fmul_rn(m11, wx0)));
            ai = __fadd_rn(ai, __fmul_rn(__ldg(inp + r11 + z1), __fmul_rn(m11, wx1)));
            out[out_base + w] = ai;

            float al = 0.0f;
            al = __fadd_rn(al, __fmul_rn(__ldg(lab + r00 + z0), __fmul_rn(m00, wx0)));
            al = __fadd_rn(al, __fmul_rn(__ldg(lab + r10 + z0), __fmul_rn(m00, wx1)));
            al = __fadd_rn(al, __fmul_rn(__ldg(lab + r01 + z0), __fmul_rn(m01, wx0)));
            al = __fadd_rn(al, __fmul_rn(__ldg(lab + r11 + z0), __fmul_rn(m01, wx1)));
            al = __fadd_rn(al, __fmul_rn(__ldg(lab + r00 + z1), __fmul_rn(m10, wx0)));
            al = __fadd_rn(al, __fmul_rn(__ldg(lab + r10 + z1), __fmul_rn(m10, wx1)));
            al = __fadd_rn(al, __fmul_rn(__ldg(lab + r01 + z1), __fmul_rn(m11, wx0)));
            al = __fadd_rn(al, __fmul_rn(__ldg(lab + r11 + z1), __fmul_rn(m11, wx1)));
            out[out_base + w + N_VOX] = (al > 0.5f) ? 1.0f : 0.0f;
        }
    }
}

extern "C" void kernel_launch(void* const* d_in, const int* in_sizes, int n_in,
                              void* d_out, int out_size)
{
    const float* inp = (const float*)d_in[0];   // input_g  [8,1,128,128,128]
    const float* lab = (const float*)d_in[1];   // label_g  [8,1,128,128,128]
    const float* T   = (const float*)d_in[2];   // transform 4x4 (16 floats)
    float* out = (float*)d_out;

    // 131072 rows, 8 rows (warps) per block
    seg_aug_kernel<<<16384, 256>>>(inp, lab, T, out);
}

// round 11
// speedup vs baseline: 2.3373x; 1.0347x over previous
#include <cuda_runtime.h>
#include <cstdint>

// Fused SegmentationAugmentation, row-hoisted, cp.async-staged, occ-6 (R11):
//   out[0 .. 2^24)     = trilinear(border) affine sample of input_g   (float)
//   out[2^24 .. 2^25)  = (same sample of label_g) > 0.5               (1.0f/0.0f)
//
// One warp per output (b,d,h) row; lane handles w = lane + 32k, k=0..3.
// T = t @ rot(z) => T[0,2] = T[1,2] = 0: x/y pipeline is row-constant.
// INPUT:  x/y blend factored per-row into smem (two-phase to halve the
//         live float4 temps) -> 2 LDS + 2 FMA per voxel.
// LABEL:  4 raw rows copied gmem->smem via cp.async; per-voxel exact
//         reference rounding chain reads bit-identical LDS copies.

#define N_VOX (1 << 24)   // 8 * 128^3

__device__ __forceinline__ float unnorm_clamp(float c)
{
    // clip(((c+1)*128 - 1)*0.5, 0, 127) with reference rounding sequence
    return fminf(fmaxf(__fmul_rn(__fsub_rn(__fmul_rn(__fadd_rn(c, 1.0f), 128.0f), 1.0f), 0.5f),
                       0.0f), 127.0f);
}

__device__ __forceinline__ void cp_async16(uint32_t smem_addr, const void* gmem)
{
    asm volatile("cp.async.cg.shared.global [%0], [%1], 16;\n"
                 :: "r"(smem_addr), "l"(gmem));
}

__global__ __launch_bounds__(256, 6)
void seg_aug_kernel(const float* __restrict__ inp,
                    const float* __restrict__ lab,
                    const float* __restrict__ T,
                    float* __restrict__ out)
{
    __shared__ float s_brow[8][128];      // blended input row per warp (4KB)
    __shared__ float s_lab[8][4][128];    // 4 raw label rows per warp (16KB)

    const int lane = threadIdx.x & 31;
    const int wid  = threadIdx.x >> 5;
    const int row  = blockIdx.x * 8 + wid;  // 131072 rows

    const int h = row & 127;
    const int d = (row >> 7) & 127;
    const int b = row >> 14;

    const float inv128 = 1.0f / 128.0f;
    const float xn = (2.0f * (float)d + 1.0f) * inv128 - 1.0f;
    const float yn = (2.0f * (float)h + 1.0f) * inv128 - 1.0f;
    const float zn0 = (2.0f * (float)lane + 1.0f) * inv128 - 1.0f;

    const float t00 = __ldg(T + 0), t01 = __ldg(T + 1), t02 = __ldg(T + 2),  t03 = __ldg(T + 3);
    const float t10 = __ldg(T + 4), t11 = __ldg(T + 5), t12 = __ldg(T + 6),  t13 = __ldg(T + 7);
    const float t20 = __ldg(T + 8), t21 = __ldg(T + 9), t22 = __ldg(T + 10), t23 = __ldg(T + 11);

    // exact reference prefixes (t0*xn + t1*yn), row-constant
    const float ux = __fadd_rn(__fmul_rn(t00, xn), __fmul_rn(t01, yn));
    const float uy = __fadd_rn(__fmul_rn(t10, xn), __fmul_rn(t11, yn));
    const float uz = __fadd_rn(__fmul_rn(t20, xn), __fmul_rn(t21, yn));

    const int out_base = row << 7;
    const int vol_base = b << 21;

    const bool fastxy = (t02 == 0.0f) && (t12 == 0.0f);   // warp-uniform

    if (fastxy) {
        // hoisted x/y pipeline (bit-exact: adding t02*zn = +/-0 can't change
        // the clamped coordinate)
        const float X = unnorm_clamp(__fadd_rn(ux, t03));
        const float Y = unnorm_clamp(__fadd_rn(uy, t13));
        const float x0f = floorf(X), y0f = floorf(Y);
        const float fx = __fsub_rn(X, x0f);
        const float fy = __fsub_rn(Y, y0f);
        const int x0 = (int)x0f, y0 = (int)y0f;
        const int x1 = min(x0 + 1, 127);
        const int y1 = min(y0 + 1, 127);
        const float wx0 = __fsub_rn(1.0f, fx), wx1 = fx;
        const float wy0 = __fsub_rn(1.0f, fy), wy1 = fy;

        const int r00 = vol_base + (x0 << 14) + (y0 << 7);  // A: (x0,y0)
        const int r10 = vol_base + (x1 << 14) + (y0 << 7);  // B: (x1,y0)
        const int r01 = vol_base + (x0 << 14) + (y1 << 7);  // C: (x0,y1)
        const int r11 = vol_base + (x1 << 14) + (y1 << 7);  // D: (x1,y1)

        // ---- stage 4 raw label rows via cp.async (no register leg) ----
        {
            const uint32_t sbase = (uint32_t)__cvta_generic_to_shared(&s_lab[wid][0][0])
                                 + (uint32_t)(lane * 16);
            cp_async16(sbase,            lab + r00 + lane * 4);
            cp_async16(sbase + 512,      lab + r10 + lane * 4);
            cp_async16(sbase + 1024,     lab + r01 + lane * 4);
            cp_async16(sbase + 1536,     lab + r11 + lane * 4);
            asm volatile("cp.async.commit_group;\n" ::: "memory");
        }

        // ---- stage blended input row, two-phase (peak 2 live float4) ----
        {
            const float wxy00 = wx0 * wy0;
            const float wxy10 = wx1 * wy0;
            float4 bl;
            {
                const float4 a = __ldg((const float4*)(inp + r00) + lane);
                const float4 c = __ldg((const float4*)(inp + r10) + lane);
                bl.x = fmaf(a.x, wxy00, c.x * wxy10);
                bl.y = fmaf(a.y, wxy00, c.y * wxy10);
                bl.z = fmaf(a.z, wxy00, c.z * wxy10);
                bl.w = fmaf(a.w, wxy00, c.w * wxy10);
            }
            const float wxy01 = wx0 * wy1;
            const float wxy11 = wx1 * wy1;
            {
                const float4 e = __ldg((const float4*)(inp + r01) + lane);
                const float4 g = __ldg((const float4*)(inp + r11) + lane);
                bl.x = fmaf(e.x, wxy01, fmaf(g.x, wxy11, bl.x));
                bl.y = fmaf(e.y, wxy01, fmaf(g.y, wxy11, bl.y));
                bl.z = fmaf(e.z, wxy01, fmaf(g.z, wxy11, bl.z));
                bl.w = fmaf(e.w, wxy01, fmaf(g.w, wxy11, bl.w));
            }
            ((float4*)s_brow[wid])[lane] = bl;
        }

        asm volatile("cp.async.wait_group 0;\n" ::: "memory");
        __syncwarp();

        const float* brow = s_brow[wid];
        const float* lA = s_lab[wid][0];   // (x0,y0)
        const float* lB = s_lab[wid][1];   // (x1,y0)
        const float* lC = s_lab[wid][2];   // (x0,y1)
        const float* lD = s_lab[wid][3];   // (x1,y1)

        #pragma unroll
        for (int k = 0; k < 4; k++) {
            const float zn = zn0 + 0.5f * (float)k;   // exact (multiples of 2^-7)
            const float zs = __fadd_rn(__fadd_rn(uz, __fmul_rn(t22, zn)), t23);
            const float Z = unnorm_clamp(zs);
            const float z0f = floorf(Z);
            const float fz = __fsub_rn(Z, z0f);
            const int z0 = (int)z0f;
            const int z1 = min(z0 + 1, 127);
            const float wz0 = __fsub_rn(1.0f, fz), wz1 = fz;

            const int idx = out_base + lane + 32 * k;

            // ---- input: 2 LDS + 2 FMA ----
            out[idx] = fmaf(brow[z0], wz0, brow[z1] * wz1);

            // ---- label: exact reference sequence (LDS sources) ----
            {
                const float m00 = __fmul_rn(wz0, wy0);
                const float m01 = __fmul_rn(wz0, wy1);
                const float m10 = __fmul_rn(wz1, wy0);
                const float m11 = __fmul_rn(wz1, wy1);
                const float wA = __fmul_rn(m00, wx0), wB = __fmul_rn(m00, wx1);
                const float wC = __fmul_rn(m01, wx0), wD = __fmul_rn(m01, wx1);
                const float wE = __fmul_rn(m10, wx0), wF = __fmul_rn(m10, wx1);
                const float wG = __fmul_rn(m11, wx0), wH = __fmul_rn(m11, wx1);
                float al = 0.0f;
                al = __fadd_rn(al, __fmul_rn(lA[z0], wA));
                al = __fadd_rn(al, __fmul_rn(lB[z0], wB));
                al = __fadd_rn(al, __fmul_rn(lC[z0], wC));
                al = __fadd_rn(al, __fmul_rn(lD[z0], wD));
                al = __fadd_rn(al, __fmul_rn(lA[z1], wE));
                al = __fadd_rn(al, __fmul_rn(lB[z1], wF));
                al = __fadd_rn(al, __fmul_rn(lC[z1], wG));
                al = __fadd_rn(al, __fmul_rn(lD[z1], wH));
                out[idx + N_VOX] = (al > 0.5f) ? 1.0f : 0.0f;
            }
        }
    } else {
        // generic exact path (not taken for this transform; kept correct)
        #pragma unroll 1
        for (int k = 0; k < 4; k++) {
            const int w = lane + 32 * k;
            const float zn = (2.0f * (float)w + 1.0f) * inv128 - 1.0f;
            const float xs = __fadd_rn(__fadd_rn(ux, __fmul_rn(t02, zn)), t03);
            const float ys = __fadd_rn(__fadd_rn(uy, __fmul_rn(t12, zn)), t13);
            const float zs = __fadd_rn(__fadd_rn(uz, __fmul_rn(t22, zn)), t23);
            const float X = unnorm_clamp(xs);
            const float Y = unnorm_clamp(ys);
            const float Z = unnorm_clamp(zs);
            const float x0f = floorf(X), y0f = floorf(Y), z0f = floorf(Z);
            const float fx = __fsub_rn(X, x0f);
            const float fy = __fsub_rn(Y, y0f);
            const float fz = __fsub_rn(Z, z0f);
            const int x0 = (int)x0f, y0 = (int)y0f, z0 = (int)z0f;
            const int x1 = min(x0 + 1, 127);
            const int y1 = min(y0 + 1, 127);
            const int z1 = min(z0 + 1, 127);
            const float wx0 = __fsub_rn(1.0f, fx), wx1 = fx;
            const float wy0 = __fsub_rn(1.0f, fy), wy1 = fy;
            const float wz0 = __fsub_rn(1.0f, fz), wz1 = fz;

            const int r00 = vol_base + (x0 << 14) + (y0 << 7);
            const int r01 = vol_base + (x0 << 14) + (y1 << 7);
            const int r10 = vol_base + (x1 << 14) + (y0 << 7);
            const int r11 = vol_base + (x1 << 14) + (y1 << 7);

            const float m00 = __fmul_rn(wz0, wy0);
            const float m01 = __fmul_rn(wz0, wy1);
            const float m10 = __fmul_rn(wz1, wy0);
            const float m11 = __fmul_rn(wz1, wy1);

            float ai = 0.0f;
            ai = __fadd_rn(ai, __fmul_rn(__ldg(inp + r00 + z0), __fmul_rn(m00, wx0)));
            ai = __fadd_rn(ai, __fmul_rn(__ldg(inp + r10 + z0), __fmul_rn(m00, wx1)));
            ai = __fadd_rn(ai, __fmul_rn(__ldg(inp + r01 + z0), __fmul_rn(m01, wx0)));
            ai = __fadd_rn(ai, __fmul_rn(__ldg(inp + r11 + z0), __fmul_rn(m01, wx1)));
            ai = __fadd_rn(ai, __fmul_rn(__ldg(inp + r00 + z1), __fmul_rn(m10, wx0)));
            ai = __fadd_rn(ai, __fmul_rn(__ldg(inp + r10 + z1), __fmul_rn(m10, wx1)));
            ai = __fadd_rn(ai, __fmul_rn(__ldg(inp + r01 + z1), __fmul_rn(m11, wx0)));
            ai = __fadd_rn(ai, __fmul_rn(__ldg(inp + r11 + z1), __fmul_rn(m11, wx1)));
            out[out_base + w] = ai;

            float al = 0.0f;
            al = __fadd_rn(al, __fmul_rn(__ldg(lab + r00 + z0), __fmul_rn(m00, wx0)));
            al = __fadd_rn(al, __fmul_rn(__ldg(lab + r10 + z0), __fmul_rn(m00, wx1)));
            al = __fadd_rn(al, __fmul_rn(__ldg(lab + r01 + z0), __fmul_rn(m01, wx0)));
            al = __fadd_rn(al, __fmul_rn(__ldg(lab + r11 + z0), __fmul_rn(m01, wx1)));
            al = __fadd_rn(al, __fmul_rn(__ldg(lab + r00 + z1), __fmul_rn(m10, wx0)));
            al = __fadd_rn(al, __fmul_rn(__ldg(lab + r10 + z1), __fmul_rn(m10, wx1)));
            al = __fadd_rn(al, __fmul_rn(__ldg(lab + r01 + z1), __fmul_rn(m11, wx0)));
            al = __fadd_rn(al, __fmul_rn(__ldg(lab + r11 + z1), __fmul_rn(m11, wx1)));
            out[out_base + w + N_VOX] = (al > 0.5f) ? 1.0f : 0.0f;
        }
    }
}

extern "C" void kernel_launch(void* const* d_in, const int* in_sizes, int n_in,
                              void* d_out, int out_size)
{
    const float* inp = (const float*)d_in[0];   // input_g  [8,1,128,128,128]
    const float* lab = (const float*)d_in[1];   // label_g  [8,1,128,128,128]
    const float* T   = (const float*)d_in[2];   // transform 4x4 (16 floats)
    float* out = (float*)d_out;

    // 131072 rows, 8 rows (warps) per block
    seg_aug_kernel<<<16384, 256>>>(inp, lab, T, out);
}